// round 1
// baseline (speedup 1.0000x reference)
#include <cuda_runtime.h>

// Global accumulators (no cudaMalloc allowed anywhere).
__device__ double g_iou_sum;
__device__ double g_valid_cnt;

__global__ void iou_init_kernel() {
    g_iou_sum = 0.0;
    g_valid_cnt = 0.0;
}

__global__ void __launch_bounds__(256)
iou_reduce_kernel(const float4* __restrict__ pred,
                  const float4* __restrict__ truth,
                  int n) {
    float lsum = 0.0f;
    float lcnt = 0.0f;

    int idx = blockIdx.x * blockDim.x + threadIdx.x;
    int stride = gridDim.x * blockDim.x;

    for (int i = idx; i < n; i += stride) {
        float4 p = __ldg(pred + i);
        float4 t = __ldg(truth + i);

        float p_x1 = p.x - p.z * 0.5f;
        float p_x2 = p.x + p.z * 0.5f;
        float p_y1 = p.y - p.w * 0.5f;
        float p_y2 = p.y + p.w * 0.5f;

        float t_x1 = t.x - t.z * 0.5f;
        float t_x2 = t.x + t.z * 0.5f;
        float t_y1 = t.y - t.w * 0.5f;
        float t_y2 = t.y + t.w * 0.5f;

        float ix = fminf(p_x2, t_x2) - fmaxf(p_x1, t_x1);
        float iy = fminf(p_y2, t_y2) - fmaxf(p_y1, t_y1);
        float inter = fmaxf(ix, 0.0f) * fmaxf(iy, 0.0f);

        float area_p = fabsf((p_x2 - p_x1) * (p_y2 - p_y1));
        float area_t = fabsf((t_x2 - t_x1) * (t_y2 - t_y1));

        float iou = inter / (area_p + area_t - inter + 1e-6f);

        bool valid = !(t.x == -1.0f && t.y == -1.0f &&
                       t.z == -1.0f && t.w == -1.0f);
        if (valid) {
            lsum += iou;
            lcnt += 1.0f;
        }
    }

    // Warp reduce
    #pragma unroll
    for (int off = 16; off > 0; off >>= 1) {
        lsum += __shfl_down_sync(0xffffffffu, lsum, off);
        lcnt += __shfl_down_sync(0xffffffffu, lcnt, off);
    }

    __shared__ float ssum[8];
    __shared__ float scnt[8];
    int warp = threadIdx.x >> 5;
    int lane = threadIdx.x & 31;
    if (lane == 0) {
        ssum[warp] = lsum;
        scnt[warp] = lcnt;
    }
    __syncthreads();

    if (warp == 0) {
        float bsum = (lane < 8) ? ssum[lane] : 0.0f;
        float bcnt = (lane < 8) ? scnt[lane] : 0.0f;
        #pragma unroll
        for (int off = 4; off > 0; off >>= 1) {
            bsum += __shfl_down_sync(0xffffffffu, bsum, off);
            bcnt += __shfl_down_sync(0xffffffffu, bcnt, off);
        }
        if (lane == 0) {
            atomicAdd(&g_iou_sum, (double)bsum);
            atomicAdd(&g_valid_cnt, (double)bcnt);
        }
    }
}

__global__ void iou_finalize_kernel(float* __restrict__ out, int out_size) {
    double c = g_valid_cnt;
    double s = g_iou_sum;
    float m = (c > 0.0) ? (float)(s / (c < 1.0 ? 1.0 : c)) : 0.0f;
    for (int i = threadIdx.x; i < out_size; i += blockDim.x) {
        out[i] = m;
    }
}

extern "C" void kernel_launch(void* const* d_in, const int* in_sizes, int n_in,
                              void* d_out, int out_size) {
    const float4* pred  = (const float4*)d_in[0];
    const float4* truth = (const float4*)d_in[1];
    // in_sizes[0] = total floats = B*NBOX*4; number of float4 boxes:
    int n = in_sizes[0] / 4;

    iou_init_kernel<<<1, 1>>>();

    int threads = 256;
    int max_blocks = 148 * 16;  // ~16 waves of CTAs per SM worth of work
    int blocks = (n + threads - 1) / threads;
    if (blocks > max_blocks) blocks = max_blocks;

    iou_reduce_kernel<<<blocks, threads>>>(pred, truth, n);
    iou_finalize_kernel<<<1, 32>>>((float*)d_out, out_size);
}